// round 15
// baseline (speedup 1.0000x reference)
#include <cuda_runtime.h>
#include <cuda_fp16.h>
#include <cstdint>

// Problem constants
#define T_LEN   4096
#define D_DIM   64
#define R_OUT   127
#define HALF_W  63

#define TT      64       // t rows per tile (M)
#define NS      192      // k halo rows staged; rows >=190 zero
#define SROWS   190

// SMEM: B (24KB, shared by all pairs) + 4 per-pair slots of 8192B.
// Slot pr: first 2048B = pair pr's private A sub-tile (rows [16pr,16pr+16));
// after pair pr's compute the same slot becomes its private band buffer
// (8128B used). No cross-pair aliasing -> no CTA-wide post-compute barrier.
// 56KB/CTA -> 3 CTAs/SM (168KB), ~59KB L1D left for the staging LDG stream.
#define SM_B      0
#define SM_PAIR   (NS * 128)                 // 24576
#define SLOT      8192
#define SM_TOTAL  (SM_PAIR + 4 * SLOT)       // 57344

#define SWZ(off) ((off) ^ (((off) >> 3) & 0x70))

// custom B swizzle: pchunk = chunk ^ (((row>>3)&3) | ((row&1)<<2))
static __device__ __forceinline__ uint32_t bswz(uint32_t row) {
    return ((row >> 3) & 3u) | ((row & 1u) << 2);
}

static __device__ __forceinline__ uint32_t smem_u32(const void* p) {
    uint32_t a;
    asm("{ .reg .u64 t; cvta.to.shared.u64 t, %1; cvt.u32.u64 %0, t; }" : "=r"(a) : "l"(p));
    return a;
}

static __device__ __forceinline__ void conv4h(float4 v, uint32_t& h0, uint32_t& h1) {
    __half2 a = __floats2half2_rn(v.x, v.y);
    __half2 b = __floats2half2_rn(v.z, v.w);
    h0 = *reinterpret_cast<uint32_t*>(&a);
    h1 = *reinterpret_cast<uint32_t*>(&b);
}

#define LDSM_X4(r0, r1, r2, r3, a) \
    asm volatile("ldmatrix.sync.aligned.m8n8.x4.shared.b16 {%0,%1,%2,%3}, [%4];" \
        : "=r"(r0), "=r"(r1), "=r"(r2), "=r"(r3) : "r"(a))

#define LDSM_X2(r0, r1, a) \
    asm volatile("ldmatrix.sync.aligned.m8n8.x2.shared.b16 {%0,%1}, [%2];" \
        : "=r"(r0), "=r"(r1) : "r"(a))

#define MMA16816(d, a0, a1, a2, a3, b0, b1) \
    asm volatile("mma.sync.aligned.m16n8k16.row.col.f32.f16.f16.f32 " \
        "{%0,%1,%2,%3}, {%4,%5,%6,%7}, {%8,%9}, {%0,%1,%2,%3};" \
        : "+f"(d[0]), "+f"(d[1]), "+f"(d[2]), "+f"(d[3]) \
        : "r"(a0), "r"(a1), "r"(a2), "r"(a3), "r"(b0), "r"(b1))

__global__ void __launch_bounds__(256, 3)
unfold_dot_hmma(const float* __restrict__ q,
                const float* __restrict__ k,
                float* __restrict__ out)
{
    extern __shared__ char smem[];
    const uint32_t sb = smem_u32(smem);
    const int tid = threadIdx.x;
    const int wid = tid >> 5;
    const int lid = tid & 31;
    const int t0  = blockIdx.x * TT;
    const int bh  = blockIdx.y;
    const int pr  = wid >> 1;          // pair index 0..3
    const int h   = wid & 1;           // half within pair
    const int m0  = pr * 16;           // 16 output rows per pair
    const uint32_t slot = sb + SM_PAIR + (uint32_t)(pr * SLOT);

    // ---- stage Q tile: 64 rows x 64 d -> fp16, into per-pair A slots ----
    const float4* qg = reinterpret_cast<const float4*>(q) +
                       ((size_t)bh * T_LEN + t0) * (D_DIM / 4);
    #pragma unroll
    for (int it = 0; it < 2; ++it) {
        int idx = tid + it * 256;          // 0..511
        int row = idx >> 3;                // 0..63
        int g   = idx & 7;
        float4 v0 = qg[row * 16 + g * 2];
        float4 v1 = qg[row * 16 + g * 2 + 1];
        uint32_t h0, h1, h2, h3;
        conv4h(v0, h0, h1);
        conv4h(v1, h2, h3);
        uint32_t dst = (uint32_t)(SM_PAIR + (row >> 4) * SLOT)
                     + SWZ((uint32_t)((row & 15) * 128 + g * 16));
        *reinterpret_cast<uint4*>(smem + dst) = make_uint4(h0, h1, h2, h3);
    }

    // ---- stage K halo: 192 rows (s = t0-63+srow), fp16, bswz swizzle ----
    const float4* kg = reinterpret_cast<const float4*>(k) +
                       (size_t)bh * T_LEN * (D_DIM / 4);
    #pragma unroll
    for (int it = 0; it < 6; ++it) {
        int idx  = tid + it * 256;         // 0..1535
        int srow = idx >> 3;
        int g    = idx & 7;
        int sg   = t0 - HALF_W + srow;
        float4 v0 = make_float4(0.f, 0.f, 0.f, 0.f);
        float4 v1 = v0;
        if (srow < SROWS && (unsigned)sg < T_LEN) {
            v0 = kg[sg * 16 + g * 2];
            v1 = kg[sg * 16 + g * 2 + 1];
        }
        uint32_t h0, h1, h2, h3;
        conv4h(v0, h0, h1);
        conv4h(v1, h2, h3);
        uint32_t off = (uint32_t)(SM_B + srow * 128) + (((uint32_t)g ^ bswz(srow)) << 4);
        *reinterpret_cast<uint4*>(smem + off) = make_uint4(h0, h1, h2, h3);
    }
    __syncthreads();           // ONLY CTA-wide barrier

    // ---- compute: D = Qh * Kh ----
    // Pair pr rows [m0,m0+16). Warp half h: supertiles s_abs = 2h+sigma
    // (cols m0+32*s_abs+8b+2p) + leftover n8 (cols m0+128+4b+2h).
    float acc[9][4];
    #pragma unroll
    for (int j = 0; j < 9; ++j)
        #pragma unroll
        for (int e = 0; e < 4; ++e) acc[j][e] = 0.f;

    // A lane address, local to the pair slot
    const int amat = lid >> 3;
    const uint32_t a_base = (uint32_t)(((amat & 1) * 8 + (lid & 7)) * 128
                                       + (amat >> 1) * 16);

    // B permuted lane constants
    const int r7    = lid & 7;
    const int khalf = (lid >> 3) & 1;
    const int phi   = (lid >> 4) & 1;
    const uint32_t row0 = (uint32_t)(m0 + 64 * h + 8 * (r7 >> 1) + (r7 & 1) + 2 * phi);
    const uint32_t row1 = row0 + 4;
    const uint32_t swz0 = bswz(row0);
    const uint32_t swz1 = bswz(row1);
    const uint32_t rowL = (uint32_t)(m0 + 128 + 4 * (r7 >> 1) + (r7 & 1) + 2 * h);
    const uint32_t swzL = bswz(rowL);

    #pragma unroll
    for (int kc = 0; kc < 4; ++kc) {
        uint32_t ah0, ah1, ah2, ah3;
        LDSM_X4(ah0, ah1, ah2, ah3, slot + SWZ(a_base + kc * 32));

        const uint32_t c0 = (uint32_t)(2 * kc + khalf);
        uint32_t ad0 = sb + SM_B + row0 * 128 + ((c0 ^ swz0) << 4);
        uint32_t ad1 = sb + SM_B + row1 * 128 + ((c0 ^ swz1) << 4);

        #pragma unroll
        for (int sg2 = 0; sg2 < 2; ++sg2) {
            uint32_t b0, b1, b2, b3;
            LDSM_X4(b0, b1, b2, b3, ad0);
            MMA16816(acc[4 * sg2 + 0], ah0, ah1, ah2, ah3, b0, b1);
            MMA16816(acc[4 * sg2 + 1], ah0, ah1, ah2, ah3, b2, b3);
            LDSM_X4(b0, b1, b2, b3, ad1);
            MMA16816(acc[4 * sg2 + 2], ah0, ah1, ah2, ah3, b0, b1);
            MMA16816(acc[4 * sg2 + 3], ah0, ah1, ah2, ah3, b2, b3);
            ad0 += 32 * 128;
            ad1 += 32 * 128;
        }
        {   // leftover n8
            uint32_t b0, b1;
            uint32_t cL = (uint32_t)(2 * kc + ((lid >> 3) & 1));
            uint32_t adL = sb + SM_B + rowL * 128 + ((cL ^ swzL) << 4);
            LDSM_X2(b0, b1, adL);
            MMA16816(acc[8], ah0, ah1, ah2, ah3, b0, b1);
        }
    }

    // pair-local barrier: both warps done reading this pair's A slot
    asm volatile("bar.sync %0, 64;" :: "r"(1 + pr) : "memory");

    // ---- epilogue: conflict-free scatter into the pair-private band slot ----
    // local band float index: il*127 + rr  (il = i - m0; parity il+rr even -> 8B ok)
    float* band = reinterpret_cast<float*>(smem + SM_PAIR + pr * SLOT);
    {
        const int il0 = (lid >> 2);
        const int cb  = lid & 3;
        #pragma unroll
        for (int sg2 = 0; sg2 < 2; ++sg2) {
            int s_abs = 2 * h + sg2;
            #pragma unroll
            for (int p = 0; p < 4; ++p) {
                int col = m0 + 32 * s_abs + 8 * cb + 2 * p;
                #pragma unroll
                for (int eh = 0; eh < 2; ++eh) {
                    int il  = il0 + 8 * eh;
                    int i   = m0 + il;
                    unsigned rr = (unsigned)(col - i);
                    int idx = il * R_OUT + (int)rr;
                    float2 v = make_float2(acc[4 * sg2 + p][2 * eh],
                                           acc[4 * sg2 + p][2 * eh + 1]);
                    if (rr <= 125u) {
                        *reinterpret_cast<float2*>(band + idx) = v;
                    } else if (rr == 126u) {
                        band[idx] = v.x;
                    } else if (rr == 0xFFFFFFFFu) {
                        band[il * R_OUT] = v.y;     // rr+1 == 0
                    }
                }
            }
        }
        {   // leftover n8: col = m0+128+4cb+2h
            int col = m0 + 128 + 4 * cb + 2 * h;
            #pragma unroll
            for (int eh = 0; eh < 2; ++eh) {
                int il  = il0 + 8 * eh;
                int i   = m0 + il;
                unsigned rr = (unsigned)(col - i);
                int idx = il * R_OUT + (int)rr;
                float2 v = make_float2(acc[8][2 * eh], acc[8][2 * eh + 1]);
                if (rr <= 125u) {
                    *reinterpret_cast<float2*>(band + idx) = v;
                } else if (rr == 126u) {
                    band[idx] = v.x;
                } else if (rr == 0xFFFFFFFFu) {
                    band[il * R_OUT] = v.y;
                }
            }
        }
    }

    // pair-local barrier, then this pair's TMA store (overlaps other pairs)
    asm volatile("bar.sync %0, 64;" :: "r"(1 + pr) : "memory");
    if (h == 0 && lid == 0) {
        asm volatile("fence.proxy.async.shared::cta;" ::: "memory");
        float* dst = out + ((size_t)bh * T_LEN + t0 + m0) * R_OUT;
        asm volatile("cp.async.bulk.global.shared::cta.bulk_group [%0], [%1], %2;"
                     :: "l"(dst), "r"(slot), "r"((uint32_t)(16 * R_OUT * 4)) : "memory");
        asm volatile("cp.async.bulk.commit_group;" ::: "memory");
        asm volatile("cp.async.bulk.wait_group.read 0;" ::: "memory");
    }
}

extern "C" void kernel_launch(void* const* d_in, const int* in_sizes, int n_in,
                              void* d_out, int out_size)
{
    const float* q = (const float*)d_in[0];
    const float* k = (const float*)d_in[1];
    float* out     = (float*)d_out;

    int bh = in_sizes[0] / (T_LEN * D_DIM);   // 128

    cudaFuncSetAttribute(unfold_dot_hmma,
                         cudaFuncAttributeMaxDynamicSharedMemorySize, SM_TOTAL);

    dim3 grid(T_LEN / TT, bh);                // (64, 128)
    unfold_dot_hmma<<<grid, 256, SM_TOTAL>>>(q, k, out);
}

// round 16
// speedup vs baseline: 1.0894x; 1.0894x over previous
#include <cuda_runtime.h>
#include <cuda_fp16.h>
#include <cstdint>

// Problem constants
#define T_LEN   4096
#define D_DIM   64
#define R_OUT   127
#define HALF_W  63

#define TT      128      // t rows per tile (M)
#define NS      256      // k halo rows staged; rows >= 254 zero
#define SROWS   254

// SMEM: A (16KB) + B (32KB) operands; band (63.5KB) aliases [0,63.5K) after
// the CTA-wide post-compute barrier. 64KB/CTA -> 2 CTAs/SM (128KB), ~96KB
// L1D intact for the staging LDG stream.
#define SM_A      0
#define SM_B      (TT * 128)                 // 16384
#define SM_BAND   0                          // aliased after compute
#define SM_TOTAL  65536

#define SWZ(off) ((off) ^ (((off) >> 3) & 0x70))

// custom B swizzle: pchunk = chunk ^ (((row>>3)&3) | ((row&1)<<2))
static __device__ __forceinline__ uint32_t bswz(uint32_t row) {
    return ((row >> 3) & 3u) | ((row & 1u) << 2);
}

static __device__ __forceinline__ uint32_t smem_u32(const void* p) {
    uint32_t a;
    asm("{ .reg .u64 t; cvta.to.shared.u64 t, %1; cvt.u32.u64 %0, t; }" : "=r"(a) : "l"(p));
    return a;
}

static __device__ __forceinline__ void conv4h(float4 v, uint32_t& h0, uint32_t& h1) {
    __half2 a = __floats2half2_rn(v.x, v.y);
    __half2 b = __floats2half2_rn(v.z, v.w);
    h0 = *reinterpret_cast<uint32_t*>(&a);
    h1 = *reinterpret_cast<uint32_t*>(&b);
}

#define LDSM_X4(r0, r1, r2, r3, a) \
    asm volatile("ldmatrix.sync.aligned.m8n8.x4.shared.b16 {%0,%1,%2,%3}, [%4];" \
        : "=r"(r0), "=r"(r1), "=r"(r2), "=r"(r3) : "r"(a))

#define LDSM_X2(r0, r1, a) \
    asm volatile("ldmatrix.sync.aligned.m8n8.x2.shared.b16 {%0,%1}, [%2];" \
        : "=r"(r0), "=r"(r1) : "r"(a))

#define MMA16816(d, a0, a1, a2, a3, b0, b1) \
    asm volatile("mma.sync.aligned.m16n8k16.row.col.f32.f16.f16.f32 " \
        "{%0,%1,%2,%3}, {%4,%5,%6,%7}, {%8,%9}, {%0,%1,%2,%3};" \
        : "+f"(d[0]), "+f"(d[1]), "+f"(d[2]), "+f"(d[3]) \
        : "r"(a0), "r"(a1), "r"(a2), "r"(a3), "r"(b0), "r"(b1))

__global__ void __launch_bounds__(512, 2)
unfold_dot_hmma(const float* __restrict__ q,
                const float* __restrict__ k,
                float* __restrict__ out)
{
    extern __shared__ char smem[];
    const uint32_t sb = smem_u32(smem);
    const int tid = threadIdx.x;
    const int wid = tid >> 5;
    const int lid = tid & 31;
    const int t0  = blockIdx.x * TT;
    const int bh  = blockIdx.y;
    const int pr  = wid >> 1;          // pair index 0..7
    const int h   = wid & 1;           // half within pair
    const int m0  = pr * 16;           // 16 output rows per pair

    // ---- stage Q tile: 128 rows x 64 d -> fp16, SW128 ----
    const float4* qg = reinterpret_cast<const float4*>(q) +
                       ((size_t)bh * T_LEN + t0) * (D_DIM / 4);
    #pragma unroll
    for (int it = 0; it < 2; ++it) {
        int idx = tid + it * 512;          // 0..1023
        int row = idx >> 3;                // 0..127
        int g   = idx & 7;
        float4 v0 = qg[row * 16 + g * 2];
        float4 v1 = qg[row * 16 + g * 2 + 1];
        uint32_t h0, h1, h2, h3;
        conv4h(v0, h0, h1);
        conv4h(v1, h2, h3);
        uint32_t off = SWZ((uint32_t)(row * 128 + g * 16));
        *reinterpret_cast<uint4*>(smem + SM_A + off) = make_uint4(h0, h1, h2, h3);
    }

    // ---- stage K halo: 256 rows (s = t0-63+srow), fp16, bswz swizzle ----
    const float4* kg = reinterpret_cast<const float4*>(k) +
                       (size_t)bh * T_LEN * (D_DIM / 4);
    #pragma unroll
    for (int it = 0; it < 4; ++it) {
        int idx  = tid + it * 512;         // 0..2047
        int srow = idx >> 3;               // 0..255
        int g    = idx & 7;
        int sg   = t0 - HALF_W + srow;
        float4 v0 = make_float4(0.f, 0.f, 0.f, 0.f);
        float4 v1 = v0;
        if (srow < SROWS && (unsigned)sg < T_LEN) {
            v0 = kg[sg * 16 + g * 2];
            v1 = kg[sg * 16 + g * 2 + 1];
        }
        uint32_t h0, h1, h2, h3;
        conv4h(v0, h0, h1);
        conv4h(v1, h2, h3);
        uint32_t off = (uint32_t)(SM_B + srow * 128) + (((uint32_t)g ^ bswz(srow)) << 4);
        *reinterpret_cast<uint4*>(smem + off) = make_uint4(h0, h1, h2, h3);
    }
    __syncthreads();

    // ---- compute: D = Qh * Kh ----
    // Pair pr rows [m0,m0+16). Warp half h: supertiles s_abs = 2h+sigma
    // (cols m0+32*s_abs+8b+2p) + leftover n8 (cols m0+128+4b+2h).
    float acc[9][4];
    #pragma unroll
    for (int j = 0; j < 9; ++j)
        #pragma unroll
        for (int e = 0; e < 4; ++e) acc[j][e] = 0.f;

    // A lane address (standard ldmatrix x4)
    const int amat = lid >> 3;
    const uint32_t a_base = (uint32_t)((m0 + (amat & 1) * 8 + (lid & 7)) * 128
                                       + (amat >> 1) * 16);

    // B permuted lane constants
    const int r7    = lid & 7;
    const int khalf = (lid >> 3) & 1;
    const int phi   = (lid >> 4) & 1;
    const uint32_t row0 = (uint32_t)(m0 + 64 * h + 8 * (r7 >> 1) + (r7 & 1) + 2 * phi);
    const uint32_t row1 = row0 + 4;
    const uint32_t swz0 = bswz(row0);
    const uint32_t swz1 = bswz(row1);
    const uint32_t rowL = (uint32_t)(m0 + 128 + 4 * (r7 >> 1) + (r7 & 1) + 2 * h);
    const uint32_t swzL = bswz(rowL);

    #pragma unroll
    for (int kc = 0; kc < 4; ++kc) {
        uint32_t ah0, ah1, ah2, ah3;
        LDSM_X4(ah0, ah1, ah2, ah3, sb + SM_A + SWZ(a_base + kc * 32));

        const uint32_t c0 = (uint32_t)(2 * kc + khalf);
        uint32_t ad0 = sb + SM_B + row0 * 128 + ((c0 ^ swz0) << 4);
        uint32_t ad1 = sb + SM_B + row1 * 128 + ((c0 ^ swz1) << 4);

        #pragma unroll
        for (int sg2 = 0; sg2 < 2; ++sg2) {
            uint32_t b0, b1, b2, b3;
            LDSM_X4(b0, b1, b2, b3, ad0);
            MMA16816(acc[4 * sg2 + 0], ah0, ah1, ah2, ah3, b0, b1);
            MMA16816(acc[4 * sg2 + 1], ah0, ah1, ah2, ah3, b2, b3);
            LDSM_X4(b0, b1, b2, b3, ad1);
            MMA16816(acc[4 * sg2 + 2], ah0, ah1, ah2, ah3, b0, b1);
            MMA16816(acc[4 * sg2 + 3], ah0, ah1, ah2, ah3, b2, b3);
            ad0 += 32 * 128;               // +32 rows: swizzle-invariant
            ad1 += 32 * 128;
        }
        {   // leftover n8
            uint32_t b0, b1;
            uint32_t cL = (uint32_t)(2 * kc + khalf);
            uint32_t adL = sb + SM_B + rowL * 128 + ((cL ^ swzL) << 4);
            LDSM_X2(b0, b1, adL);
            MMA16816(acc[8], ah0, ah1, ah2, ah3, b0, b1);
        }
    }

    __syncthreads();   // band aliases operand tiles

    // ---- epilogue: conflict-free paired scatter into smem band tile ----
    // band float index: i*126 + col  (== i*127 + rr, rr = col - i)
    float* band = reinterpret_cast<float*>(smem + SM_BAND);
    {
        const int i0 = m0 + (lid >> 2);
        const int cb = lid & 3;
        #pragma unroll
        for (int sg2 = 0; sg2 < 2; ++sg2) {
            int s_abs = 2 * h + sg2;
            #pragma unroll
            for (int p = 0; p < 4; ++p) {
                int col = m0 + 32 * s_abs + 8 * cb + 2 * p;
                #pragma unroll
                for (int eh = 0; eh < 2; ++eh) {
                    int i   = i0 + 8 * eh;
                    int idx = i * (R_OUT - 1) + col;
                    unsigned rr = (unsigned)(col - i);
                    float2 v = make_float2(acc[4 * sg2 + p][2 * eh],
                                           acc[4 * sg2 + p][2 * eh + 1]);
                    if (rr <= 125u) {
                        *reinterpret_cast<float2*>(band + idx) = v;
                    } else if (rr == 126u) {
                        band[idx] = v.x;
                    } else if (rr == 0xFFFFFFFFu) {
                        band[idx + 1] = v.y;
                    }
                }
            }
        }
        {   // leftover n8: col = m0+128+4cb+2h
            int col = m0 + 128 + 4 * cb + 2 * h;
            #pragma unroll
            for (int eh = 0; eh < 2; ++eh) {
                int i   = i0 + 8 * eh;
                int idx = i * (R_OUT - 1) + col;
                unsigned rr = (unsigned)(col - i);
                float2 v = make_float2(acc[8][2 * eh], acc[8][2 * eh + 1]);
                if (rr <= 125u) {
                    *reinterpret_cast<float2*>(band + idx) = v;
                } else if (rr == 126u) {
                    band[idx] = v.x;
                } else if (rr == 0xFFFFFFFFu) {
                    band[idx + 1] = v.y;
                }
            }
        }
    }

    // ---- per-pair bulk store: pair's 16 rows = contiguous 8128B slice ----
    asm volatile("bar.sync %0, 64;" :: "r"(1 + pr) : "memory");
    if (h == 0 && lid == 0) {
        asm volatile("fence.proxy.async.shared::cta;" ::: "memory");
        float* dst = out + ((size_t)bh * T_LEN + t0 + m0) * R_OUT;
        uint32_t src = sb + SM_BAND + (uint32_t)(m0 * R_OUT * 4);
        asm volatile("cp.async.bulk.global.shared::cta.bulk_group [%0], [%1], %2;"
                     :: "l"(dst), "r"(src), "r"((uint32_t)(16 * R_OUT * 4)) : "memory");
        asm volatile("cp.async.bulk.commit_group;" ::: "memory");
        asm volatile("cp.async.bulk.wait_group.read 0;" ::: "memory");
    }
}

extern "C" void kernel_launch(void* const* d_in, const int* in_sizes, int n_in,
                              void* d_out, int out_size)
{
    const float* q = (const float*)d_in[0];
    const float* k = (const float*)d_in[1];
    float* out     = (float*)d_out;

    int bh = in_sizes[0] / (T_LEN * D_DIM);   // 128

    cudaFuncSetAttribute(unfold_dot_hmma,
                         cudaFuncAttributeMaxDynamicSharedMemorySize, SM_TOTAL);

    dim3 grid(T_LEN / TT, bh);                // (32, 128)
    unfold_dot_hmma<<<grid, 512, SM_TOTAL>>>(q, k, out);
}